// round 11
// baseline (speedup 1.0000x reference)
#include <cuda_runtime.h>
#include <cuda_fp16.h>
#include <cstdint>
#include <math.h>

#define BB    8
#define CIN   256
#define COUT  256
#define NP    8192
#define KT    9
#define DILT  6
#define PADT  24
#define NCHUNK 36          // (KT * CIN) / 64

// ---------------- device scratch ----------------
__device__ float   g_gw[BB * KT * NP];              // gate weights [b][k][n]
__device__ uint8_t g_A8[2 * NCHUNK * 16384];        // pre-swizzled fp16 W tiles
__device__ float   g_sum[COUT];
__device__ float   g_sumsq[COUT];
__device__ float   g_scale[COUT];
__device__ float   g_shift[COUT];

// ---------------- helpers ----------------
__device__ __forceinline__ uint32_t smem_u32(const void* p) {
    uint32_t a;
    asm("{ .reg .u64 t; cvta.to.shared.u64 t, %1; cvt.u32.u64 %0, t; }" : "=r"(a) : "l"(p));
    return a;
}
#define SW128(off) ((off) ^ (((off) >> 3) & 0x70))

__device__ __forceinline__ void cp16(uint32_t dst, const void* src) {
    asm volatile("cp.async.cg.shared.global [%0], [%1], 16;" :: "r"(dst), "l"(src));
}
__device__ __forceinline__ void ldsm_x4(uint32_t* r, uint32_t addr) {
    asm volatile("ldmatrix.sync.aligned.m8n8.x4.shared.b16 {%0,%1,%2,%3}, [%4];"
        : "=r"(r[0]), "=r"(r[1]), "=r"(r[2]), "=r"(r[3]) : "r"(addr));
}
__device__ __forceinline__ void ldsm_x4t(uint32_t* r, uint32_t addr) {
    asm volatile("ldmatrix.sync.aligned.m8n8.x4.trans.shared.b16 {%0,%1,%2,%3}, [%4];"
        : "=r"(r[0]), "=r"(r[1]), "=r"(r[2]), "=r"(r[3]) : "r"(addr));
}
__device__ __forceinline__ void mma16816(float* c, const uint32_t* a, uint32_t b0, uint32_t b1) {
    asm volatile(
        "mma.sync.aligned.m16n8k16.row.col.f32.f16.f16.f32 "
        "{%0,%1,%2,%3}, {%4,%5,%6,%7}, {%8,%9}, {%0,%1,%2,%3};"
        : "+f"(c[0]), "+f"(c[1]), "+f"(c[2]), "+f"(c[3])
        : "r"(a[0]), "r"(a[1]), "r"(a[2]), "r"(a[3]), "r"(b0), "r"(b1));
}

// ---------------- kernel 0 ----------------
__global__ void zero_sums_kernel() {
    int t = threadIdx.x;
    g_sum[t] = 0.f;
    g_sumsq[t] = 0.f;
}

// ---------------- kernel 1: tap gate weights ----------------
__global__ void gweight_kernel(const float* __restrict__ coords,
                               const float* __restrict__ rot,
                               const float* __restrict__ dist) {
    int n = blockIdx.x * blockDim.x + threadIdx.x;
    int b = blockIdx.y;
    const float* cb = coords + (size_t)b * 3 * NP;
    const float* rb = rot    + (size_t)b * 3 * NP;

    float c0x = cb[n], c0y = cb[NP + n], c0z = cb[2 * NP + n];
    float r0x = rb[n], r0y = rb[NP + n], r0z = rb[2 * NP + n];
    float d0  = dist[(size_t)b * NP + n];
    float r0sq = r0x * r0x + r0y * r0y + r0z * r0z;

#pragma unroll
    for (int k = 0; k < KT; k++) {
        int j = n + k * DILT - PADT;
        float cjx = 0.f, cjy = 0.f, cjz = 0.f;
        float rjx = 0.f, rjy = 0.f, rjz = 0.f;
        float dj  = 0.f;
        if (j >= 0 && j < NP) {
            cjx = cb[j]; cjy = cb[NP + j]; cjz = cb[2 * NP + j];
            rjx = rb[j]; rjy = rb[NP + j]; rjz = rb[2 * NP + j];
            dj  = dist[(size_t)b * NP + j];
        }
        float dx = c0x - cjx, dy = c0y - cjy, dz = c0z - cjz;
        float dc = dx * dx + dy * dy + dz * dz;
        float dd = (d0 - dj) * (d0 - dj);
        float g  = expf(-0.5f * (dc + dd));
        float num  = r0x * rjx + r0y * rjy + r0z * rjz;
        float rjsq = rjx * rjx + rjy * rjy + rjz * rjz;
        float den  = sqrtf(r0sq * rjsq) + 1e-8f;
        g_gw[((size_t)b * KT + k) * NP + n] = g * fabsf(num / den);
    }
}

// ---------------- kernel 2: fp16 pre-swizzled W ----------------
__global__ void wsplit_kernel(const float* __restrict__ W) {
    int idx = blockIdx.x * 256 + threadIdx.x;
    if (idx >= 2 * NCHUNK * 128 * 64) return;
    int kc    = idx & 63;
    int t     = idx >> 6;
    int o_in  = t & 127;
    int t2    = t >> 7;
    int chunk = t2 % NCHUNK;
    int otile = t2 / NCHUNK;
    int k = chunk >> 2;
    int c = ((chunk & 3) << 6) + kc;
    int o = (otile << 7) + o_in;
    float val = W[((size_t)o * CIN + c) * KT + k];
    uint32_t sw = SW128((uint32_t)(o_in * 128 + kc * 2));
    size_t tb = (size_t)(otile * NCHUNK + chunk) * 16384;
    *(__half*)&g_A8[tb + sw] = __float2half(val);
}

// ---------------- SMEM layout ----------------
#define OFF_A   0          // 2 bufs x 16KB fp16 W                   = 32768
#define OFF_B   32768      // 2 bufs x 32KB fp16 gated x (2 subtiles) = 65536
#define OFF_ST  98304      // stats: 256 floats
#define SMEM_TOTAL 99328

// ---- load raw x of chunk s into 32 regs (8 float4) ----
// thread owns cols [nn, nn+4), rows r0+8*it (it<8): self-mapped, no smem staging.
__device__ __forceinline__ void loadV(float4* vr,
                                      const float* __restrict__ xb,
                                      int n_base, int s, int tid) {
    const int off = (s >> 2) * DILT - PADT;
    const int c0  = (s & 3) << 6;
    const int nn  = (tid & 63) << 2;             // float col 0..252
    const int r0  = tid >> 6;                    // base row 0..7
    const int src = n_base + off + nn;
    const float* gs = xb + (size_t)(c0 + r0) * NP + src;

    if (src >= 0 && src + 3 < NP) {              // interior
        if ((off & 3) == 0) {                    // 16B-aligned tap (even k)
#pragma unroll
            for (int it = 0; it < 8; it++)
                vr[it] = *(const float4*)(gs + (size_t)it * 8 * NP);
        } else {                                 // 8B-aligned tap (odd k)
#pragma unroll
            for (int it = 0; it < 8; it++) {
                const float* gp = gs + (size_t)it * 8 * NP;
                float2 p0 = *(const float2*)gp;
                float2 p1 = *(const float2*)(gp + 2);
                vr[it] = make_float4(p0.x, p0.y, p1.x, p1.y);
            }
        }
    } else if (src + 3 < 0 || src >= NP) {       // fully OOB
#pragma unroll
        for (int it = 0; it < 8; it++)
            vr[it] = make_float4(0.f, 0.f, 0.f, 0.f);
    } else {                                     // straddle (rare)
#pragma unroll
        for (int it = 0; it < 8; it++) {
            const float* gp = gs + (size_t)it * 8 * NP;
            float e0 = (src + 0 >= 0 && src + 0 < NP) ? gp[0] : 0.f;
            float e1 = (src + 1 >= 0 && src + 1 < NP) ? gp[1] : 0.f;
            float e2 = (src + 2 >= 0 && src + 2 < NP) ? gp[2] : 0.f;
            float e3 = (src + 3 >= 0 && src + 3 < NP) ? gp[3] : 0.f;
            vr[it] = make_float4(e0, e1, e2, e3);
        }
    }
}

// ---- gate + fp16 + STS into B[buf] (two 128-n subtiles, 256B rows, swizzled) ----
__device__ __forceinline__ void convertB(char* smem, uint32_t bofs, const float4* vr,
                                         int b, int n_base, int s, int tid) {
    const int kk  = s >> 2;
    const int nn  = (tid & 63) << 2;
    const int r0  = tid >> 6;
    const int sub = nn >> 7;                     // 0 or 1 (n-subtile)
    const int nnl = nn & 127;
    const float4 g4 = *(const float4*)(g_gw + ((size_t)b * KT + kk) * NP + n_base + nn);
    char* bp = smem + bofs + sub * 16384;
#pragma unroll
    for (int it = 0; it < 8; it++) {
        int row = r0 + it * 8;
        float4 v = vr[it];
        __half2 h01 = __floats2half2_rn(v.x * g4.x, v.y * g4.y);
        __half2 h23 = __floats2half2_rn(v.z * g4.z, v.w * g4.w);
        uint32_t ofs = (uint32_t)(row * 256) + (((uint32_t)(nnl * 2)) ^ ((uint32_t)(row & 7) << 4));
        *(uint2*)(bp + ofs) = make_uint2(*(uint32_t*)&h01, *(uint32_t*)&h23);
    }
}

// ---------------- kernel 3: HMMA fused gated dilated conv (512 thr, 128x256 tile) ----
__global__ void __launch_bounds__(512, 1) conv9_kernel(
    const float* __restrict__ x,
    const float* __restrict__ bias,
    float* __restrict__ out) {

    extern __shared__ __align__(16) char smem[];
    const uint32_t sbase = smem_u32(smem);

    const int tid  = threadIdx.x;
    const int lane = tid & 31;
    const int wid  = tid >> 5;            // 0..15
    const int wm = wid & 3;               // 4 m-warps (32 rows each)
    const int wn = wid >> 2;              // 4 n-warps (64 cols each)
    const int g  = lane >> 2;
    const int tg = lane & 3;

    const int b      = blockIdx.z;
    const int n_base = blockIdx.x * 256;
    const int otile  = blockIdx.y;
    const int o_base = otile * 128;

    const float*   xb   = x + (size_t)b * CIN * NP;
    const uint8_t* Asrc = g_A8 + (size_t)otile * NCHUNK * 16384;

    const int a_row   = wm * 32 + ((lane >> 3) & 1) * 8 + (lane & 7);
    const int a_kb    = ((lane >> 4) & 1) * 16;
    const int b_nbyte = (wn & 1) * 128 + ((lane >> 4) << 4);
    const int b_sub   = (wn >> 1) * 16384;
    const int b_kcl   = lane & 15;

    float acc[2][8][4];
#pragma unroll
    for (int mt = 0; mt < 2; mt++)
#pragma unroll
        for (int nt = 0; nt < 8; nt++)
#pragma unroll
            for (int r = 0; r < 4; r++) acc[mt][nt][r] = 0.f;

    float4 vr[8];

    // ---- prologue ----
    {
        const uint8_t* as = Asrc + tid * 32;
        cp16(sbase + OFF_A + tid * 32,      as);
        cp16(sbase + OFF_A + tid * 32 + 16, as + 16);
        asm volatile("cp.async.commit_group;");
        loadV(vr, xb, n_base, 0, tid);
        asm volatile("cp.async.wait_group 0;" ::: "memory");   // A[0] landed
        convertB(smem, OFF_B, vr, b, n_base, 0, tid);
        __syncthreads();                                       // A[0], B[0] visible
        const uint8_t* as1 = Asrc + 16384 + tid * 32;
        cp16(sbase + OFF_A + 16384 + tid * 32,      as1);
        cp16(sbase + OFF_A + 16384 + tid * 32 + 16, as1 + 16);
        asm volatile("cp.async.commit_group;");
    }

    // ---- mainloop: one sync per chunk ----
    for (int i = 0; i < NCHUNK; i++) {
        const int cur = i & 1;

        if (i + 1 < NCHUNK) loadV(vr, xb, n_base, i + 1, tid);   // LDG -> regs (hidden)

        // compute chunk i from A[cur], B[cur]
        {
            const uint32_t Ab = sbase + OFF_A + cur * 16384;
            const uint32_t Bb = sbase + OFF_B + cur * 32768 + b_sub;
#pragma unroll
            for (int ks = 0; ks < 4; ks++) {
                uint32_t ah[2][4];
#pragma unroll
                for (int mt = 0; mt < 2; mt++) {
                    uint32_t byte = (uint32_t)((a_row + mt * 16) * 128 + ks * 32 + a_kb);
                    ldsm_x4(ah[mt], Ab + SW128(byte));
                }
                const int kc = ks * 16 + b_kcl;
                const uint32_t kb = (uint32_t)kc * 256;
                const uint32_t xm = ((uint32_t)kc & 7) << 4;
#pragma unroll
                for (int nt2 = 0; nt2 < 4; nt2++) {
                    uint32_t br[4];
                    const uint32_t nb = (uint32_t)(b_nbyte + nt2 * 32);
                    ldsm_x4t(br, Bb + kb + (nb ^ xm));
#pragma unroll
                    for (int mt = 0; mt < 2; mt++) {
                        mma16816(acc[mt][nt2 * 2 + 0], ah[mt], br[0], br[1]);
                        mma16816(acc[mt][nt2 * 2 + 1], ah[mt], br[2], br[3]);
                    }
                }
            }
        }

        if (i + 1 < NCHUNK)
            convertB(smem, OFF_B + (cur ^ 1) * 32768, vr, b, n_base, i + 1, tid);

        asm volatile("cp.async.wait_group 0;" ::: "memory");   // A[i+1] landed
        __syncthreads();    // B[nxt] + A[i+1] visible; A[cur] free
        if (i + 2 < NCHUNK) {
            const uint8_t* as = Asrc + (size_t)(i + 2) * 16384 + tid * 32;
            const uint32_t ad = sbase + OFF_A + cur * 16384 + tid * 32;
            cp16(ad,      as);
            cp16(ad + 16, as + 16);
            asm volatile("cp.async.commit_group;");
        }
    }

    // ---- epilogue ----
    float* bst = (float*)(smem + OFF_ST);
    if (tid < 256) bst[tid] = 0.f;
    __syncthreads();

    float s4[4] = {0.f, 0.f, 0.f, 0.f}, q4[4] = {0.f, 0.f, 0.f, 0.f};
#pragma unroll
    for (int mt = 0; mt < 2; mt++) {
        const int r0v = wm * 32 + mt * 16 + g;
        const int r1v = r0v + 8;
        const float b0v = bias[o_base + r0v];
        const float b1v = bias[o_base + r1v];
        float* p0 = out + ((size_t)b * COUT + o_base + r0v) * NP + n_base + wn * 64 + 2 * tg;
        float* p1 = out + ((size_t)b * COUT + o_base + r1v) * NP + n_base + wn * 64 + 2 * tg;
#pragma unroll
        for (int nt = 0; nt < 8; nt++) {
            float v0 = acc[mt][nt][0] + b0v;
            float v1 = acc[mt][nt][1] + b0v;
            float v2 = acc[mt][nt][2] + b1v;
            float v3 = acc[mt][nt][3] + b1v;
            *(float2*)(p0 + nt * 8) = make_float2(v0, v1);
            *(float2*)(p1 + nt * 8) = make_float2(v2, v3);
            s4[mt * 2 + 0] += v0 + v1;  q4[mt * 2 + 0] += v0 * v0 + v1 * v1;
            s4[mt * 2 + 1] += v2 + v3;  q4[mt * 2 + 1] += v2 * v2 + v3 * v3;
        }
    }
#pragma unroll
    for (int r = 0; r < 4; r++) {
        float s = s4[r], q = q4[r];
        s += __shfl_xor_sync(0xffffffffu, s, 1);
        s += __shfl_xor_sync(0xffffffffu, s, 2);
        q += __shfl_xor_sync(0xffffffffu, q, 1);
        q += __shfl_xor_sync(0xffffffffu, q, 2);
        if (tg == 0) {
            int lr = wm * 32 + (r >> 1) * 16 + (r & 1) * 8 + g;
            atomicAdd(&bst[lr], s);
            atomicAdd(&bst[128 + lr], q);
        }
    }
    __syncthreads();
    if (tid < 128) {
        atomicAdd(&g_sum[o_base + tid],   bst[tid]);
        atomicAdd(&g_sumsq[o_base + tid], bst[128 + tid]);
    }
}

// ---------------- kernel 4: finalize BN stats ----------------
__global__ void stats_kernel(const float* __restrict__ gamma,
                             const float* __restrict__ beta) {
    int c = threadIdx.x;
    const float inv_n = 1.0f / (float)(BB * NP);
    float mean = g_sum[c] * inv_n;
    float var  = g_sumsq[c] * inv_n - mean * mean;
    float inv  = 1.0f / sqrtf(var + 1e-5f);
    float sc   = gamma[c] * inv;
    g_scale[c] = sc;
    g_shift[c] = beta[c] - mean * sc;
}

// ---------------- kernel 5: apply BN + ReLU ----------------
__global__ void apply_kernel(float* __restrict__ out) {
    size_t i4 = (size_t)blockIdx.x * blockDim.x + threadIdx.x;
    float4 v = ((float4*)out)[i4];
    int o = (int)((i4 * 4) >> 13) & (COUT - 1);
    float s = g_scale[o], t = g_shift[o];
    v.x = fmaxf(v.x * s + t, 0.f);
    v.y = fmaxf(v.y * s + t, 0.f);
    v.z = fmaxf(v.z * s + t, 0.f);
    v.w = fmaxf(v.w * s + t, 0.f);
    ((float4*)out)[i4] = v;
}

// ---------------- launch ----------------
extern "C" void kernel_launch(void* const* d_in, const int* in_sizes, int n_in,
                              void* d_out, int out_size) {
    const float* x      = (const float*)d_in[0];
    const float* coords = (const float*)d_in[1];
    const float* rot    = (const float*)d_in[2];
    const float* dist   = (const float*)d_in[3];
    const float* W      = (const float*)d_in[4];
    const float* bias   = (const float*)d_in[5];
    const float* gamma  = (const float*)d_in[6];
    const float* beta   = (const float*)d_in[7];
    float* out = (float*)d_out;

    cudaFuncSetAttribute(conv9_kernel, cudaFuncAttributeMaxDynamicSharedMemorySize, SMEM_TOTAL);

    zero_sums_kernel<<<1, 256>>>();
    gweight_kernel<<<dim3(NP / 256, BB), 256>>>(coords, rot, dist);
    wsplit_kernel<<<(2 * NCHUNK * 128 * 64 + 255) / 256, 256>>>(W);
    conv9_kernel<<<dim3(NP / 256, COUT / 128, BB), 512, SMEM_TOTAL>>>(x, bias, out);
    stats_kernel<<<1, 256>>>(gamma, beta);
    apply_kernel<<<(BB * COUT * NP / 4) / 256, 256>>>(out);
}

// round 13
// speedup vs baseline: 1.2052x; 1.2052x over previous
#include <cuda_runtime.h>
#include <cuda_fp16.h>
#include <cstdint>
#include <math.h>

#define BB    8
#define CIN   256
#define COUT  256
#define NP    8192
#define KT    9
#define DILT  6
#define PADT  24
#define NCHUNK 36          // (KT * CIN) / 64

// ---------------- device scratch ----------------
__device__ float   g_gw[BB * KT * NP];              // gate weights [b][k][n]
__device__ uint8_t g_A8[2 * NCHUNK * 16384];        // pre-swizzled fp16 W tiles
__device__ float   g_sum[COUT];
__device__ float   g_sumsq[COUT];
__device__ float   g_scale[COUT];
__device__ float   g_shift[COUT];

// ---------------- helpers ----------------
__device__ __forceinline__ uint32_t smem_u32(const void* p) {
    uint32_t a;
    asm("{ .reg .u64 t; cvta.to.shared.u64 t, %1; cvt.u32.u64 %0, t; }" : "=r"(a) : "l"(p));
    return a;
}
#define SW128(off) ((off) ^ (((off) >> 3) & 0x70))

__device__ __forceinline__ void cp16(uint32_t dst, const void* src) {
    asm volatile("cp.async.cg.shared.global [%0], [%1], 16;" :: "r"(dst), "l"(src));
}
__device__ __forceinline__ void ldsm_x4(uint32_t* r, uint32_t addr) {
    asm volatile("ldmatrix.sync.aligned.m8n8.x4.shared.b16 {%0,%1,%2,%3}, [%4];"
        : "=r"(r[0]), "=r"(r[1]), "=r"(r[2]), "=r"(r[3]) : "r"(addr));
}
__device__ __forceinline__ void ldsm_x4t(uint32_t* r, uint32_t addr) {
    asm volatile("ldmatrix.sync.aligned.m8n8.x4.trans.shared.b16 {%0,%1,%2,%3}, [%4];"
        : "=r"(r[0]), "=r"(r[1]), "=r"(r[2]), "=r"(r[3]) : "r"(addr));
}
__device__ __forceinline__ void mma16816(float* c, const uint32_t* a, uint32_t b0, uint32_t b1) {
    asm volatile(
        "mma.sync.aligned.m16n8k16.row.col.f32.f16.f16.f32 "
        "{%0,%1,%2,%3}, {%4,%5,%6,%7}, {%8,%9}, {%0,%1,%2,%3};"
        : "+f"(c[0]), "+f"(c[1]), "+f"(c[2]), "+f"(c[3])
        : "r"(a[0]), "r"(a[1]), "r"(a[2]), "r"(a[3]), "r"(b0), "r"(b1));
}

// ---------------- kernel 0 ----------------
__global__ void zero_sums_kernel() {
    int t = threadIdx.x;
    g_sum[t] = 0.f;
    g_sumsq[t] = 0.f;
}

// ---------------- kernel 1: tap gate weights ----------------
__global__ void gweight_kernel(const float* __restrict__ coords,
                               const float* __restrict__ rot,
                               const float* __restrict__ dist) {
    int n = blockIdx.x * blockDim.x + threadIdx.x;
    int b = blockIdx.y;
    const float* cb = coords + (size_t)b * 3 * NP;
    const float* rb = rot    + (size_t)b * 3 * NP;

    float c0x = cb[n], c0y = cb[NP + n], c0z = cb[2 * NP + n];
    float r0x = rb[n], r0y = rb[NP + n], r0z = rb[2 * NP + n];
    float d0  = dist[(size_t)b * NP + n];
    float r0sq = r0x * r0x + r0y * r0y + r0z * r0z;

#pragma unroll
    for (int k = 0; k < KT; k++) {
        int j = n + k * DILT - PADT;
        float cjx = 0.f, cjy = 0.f, cjz = 0.f;
        float rjx = 0.f, rjy = 0.f, rjz = 0.f;
        float dj  = 0.f;
        if (j >= 0 && j < NP) {
            cjx = cb[j]; cjy = cb[NP + j]; cjz = cb[2 * NP + j];
            rjx = rb[j]; rjy = rb[NP + j]; rjz = rb[2 * NP + j];
            dj  = dist[(size_t)b * NP + j];
        }
        float dx = c0x - cjx, dy = c0y - cjy, dz = c0z - cjz;
        float dc = dx * dx + dy * dy + dz * dz;
        float dd = (d0 - dj) * (d0 - dj);
        float g  = expf(-0.5f * (dc + dd));
        float num  = r0x * rjx + r0y * rjy + r0z * rjz;
        float rjsq = rjx * rjx + rjy * rjy + rjz * rjz;
        float den  = sqrtf(r0sq * rjsq) + 1e-8f;
        g_gw[((size_t)b * KT + k) * NP + n] = g * fabsf(num / den);
    }
}

// ---------------- kernel 2: fp16 pre-swizzled W ----------------
__global__ void wsplit_kernel(const float* __restrict__ W) {
    int idx = blockIdx.x * 256 + threadIdx.x;
    if (idx >= 2 * NCHUNK * 128 * 64) return;
    int kc    = idx & 63;
    int t     = idx >> 6;
    int o_in  = t & 127;
    int t2    = t >> 7;
    int chunk = t2 % NCHUNK;
    int otile = t2 / NCHUNK;
    int k = chunk >> 2;
    int c = ((chunk & 3) << 6) + kc;
    int o = (otile << 7) + o_in;
    float val = W[((size_t)o * CIN + c) * KT + k];
    uint32_t sw = SW128((uint32_t)(o_in * 128 + kc * 2));
    size_t tb = (size_t)(otile * NCHUNK + chunk) * 16384;
    *(__half*)&g_A8[tb + sw] = __float2half(val);
}

// ---------------- SMEM layout ----------------
#define OFF_A   0          // 2 bufs x 16KB fp16 W          = 32768
#define OFF_B   32768      // 2 bufs x 16KB fp16 gated x    = 32768
#define OFF_ST  65536      // stats: 256 floats
#define SMEM_TOTAL 66560

// ---- load half (4 row-groups) of raw x for chunk s into 4 float4 regs ----
// thread owns cols [nn, nn+4), kc rows (tid>>5) + h*32 + 8*it, it<4.
__device__ __forceinline__ void loadVh(float4* vr,
                                       const float* __restrict__ xb,
                                       int n_base, int s, int tid, int h) {
    const int off = (s >> 2) * DILT - PADT;
    const int c0  = (s & 3) << 6;
    const int nn  = (tid & 31) << 2;
    const int r0h = (tid >> 5) + h * 32;
    const int src = n_base + off + nn;
    const float* gs = xb + (size_t)(c0 + r0h) * NP + src;

    if (src >= 0 && src + 3 < NP) {              // interior
        if ((off & 3) == 0) {                    // 16B-aligned tap (even k)
#pragma unroll
            for (int it = 0; it < 4; it++)
                vr[it] = *(const float4*)(gs + (size_t)it * 8 * NP);
        } else {                                 // 8B-aligned tap (odd k)
#pragma unroll
            for (int it = 0; it < 4; it++) {
                const float* gp = gs + (size_t)it * 8 * NP;
                float2 p0 = *(const float2*)gp;
                float2 p1 = *(const float2*)(gp + 2);
                vr[it] = make_float4(p0.x, p0.y, p1.x, p1.y);
            }
        }
    } else if (src + 3 < 0 || src >= NP) {       // fully OOB
#pragma unroll
        for (int it = 0; it < 4; it++)
            vr[it] = make_float4(0.f, 0.f, 0.f, 0.f);
    } else {                                     // straddle (rare edge)
#pragma unroll
        for (int it = 0; it < 4; it++) {
            const float* gp = gs + (size_t)it * 8 * NP;
            float e0 = (src + 0 >= 0 && src + 0 < NP) ? gp[0] : 0.f;
            float e1 = (src + 1 >= 0 && src + 1 < NP) ? gp[1] : 0.f;
            float e2 = (src + 2 >= 0 && src + 2 < NP) ? gp[2] : 0.f;
            float e3 = (src + 3 >= 0 && src + 3 < NP) ? gp[3] : 0.f;
            vr[it] = make_float4(e0, e1, e2, e3);
        }
    }
}

// ---- gate + fp16 + STS half into B tile ([kc 64][n 128], 256B swizzled rows) ----
// bofs is a BYTE OFFSET from smem base (NOT a shared-window address).
__device__ __forceinline__ void convertBh(char* smem, uint32_t bofs, const float4* vr,
                                          int b, int n_base, int s, int tid, int h) {
    const int kk  = s >> 2;
    const int nn  = (tid & 31) << 2;
    const int r0h = (tid >> 5) + h * 32;
    const float4 g4 = *(const float4*)(g_gw + ((size_t)b * KT + kk) * NP + n_base + nn);
#pragma unroll
    for (int it = 0; it < 4; it++) {
        int row = r0h + it * 8;
        float4 v = vr[it];
        __half2 h01 = __floats2half2_rn(v.x * g4.x, v.y * g4.y);
        __half2 h23 = __floats2half2_rn(v.z * g4.z, v.w * g4.w);
        uint32_t ofs = (uint32_t)(row * 256) + (((uint32_t)(nn * 2)) ^ ((uint32_t)(row & 7) << 4));
        *(uint2*)(smem + bofs + ofs) = make_uint2(*(uint32_t*)&h01, *(uint32_t*)&h23);
    }
}

// ---------------- kernel 3: HMMA fused gated dilated conv ----------------
__global__ void __launch_bounds__(256, 2) conv11_kernel(
    const float* __restrict__ x,
    const float* __restrict__ bias,
    float* __restrict__ out) {

    extern __shared__ __align__(16) char smem[];
    const uint32_t sbase = smem_u32(smem);

    const int tid  = threadIdx.x;
    const int lane = tid & 31;
    const int wid  = tid >> 5;
    const int wm = wid & 3;
    const int wn = wid >> 2;
    const int g  = lane >> 2;
    const int tg = lane & 3;

    const int b      = blockIdx.z;
    const int n_base = blockIdx.x * 128;
    const int otile  = blockIdx.y;
    const int o_base = otile * 128;

    const float*   xb   = x + (size_t)b * CIN * NP;
    const uint8_t* Asrc = g_A8 + (size_t)otile * NCHUNK * 16384;

    const int a_row   = wm * 32 + ((lane >> 3) & 1) * 8 + (lane & 7);
    const int a_kb    = ((lane >> 4) & 1) * 16;
    const int b_nbyte = wn * 128 + ((lane >> 4) << 4);
    const int b_kcl   = lane & 15;

    float acc[2][8][4];
#pragma unroll
    for (int mt = 0; mt < 2; mt++)
#pragma unroll
        for (int nt = 0; nt < 8; nt++)
#pragma unroll
            for (int r = 0; r < 4; r++) acc[mt][nt][r] = 0.f;

    float4 vr[4];

    // ---- prologue ----
    {
        const uint8_t* as = Asrc + tid * 16;
#pragma unroll
        for (int q = 0; q < 4; q++) cp16(sbase + OFF_A + tid * 16 + q * 4096, as + q * 4096);
        asm volatile("cp.async.commit_group;");
        loadVh(vr, xb, n_base, 0, tid, 0);
        convertBh(smem, OFF_B, vr, b, n_base, 0, tid, 0);
        loadVh(vr, xb, n_base, 0, tid, 1);
        convertBh(smem, OFF_B, vr, b, n_base, 0, tid, 1);
        asm volatile("cp.async.wait_group 0;" ::: "memory");   // A[0] landed
        __syncthreads();                                       // A[0], B[0] visible
        const uint8_t* as1 = Asrc + 16384 + tid * 16;
#pragma unroll
        for (int q = 0; q < 4; q++) cp16(sbase + OFF_A + 16384 + tid * 16 + q * 4096, as1 + q * 4096);
        asm volatile("cp.async.commit_group;");
    }

    // ---- mainloop: one sync per chunk, LDG prefetch interleaved with MMA halves ----
    for (int i = 0; i < NCHUNK; i++) {
        const int  cur = i & 1;
        const bool hn  = (i + 1 < NCHUNK);
        const uint32_t Ab    = sbase + OFF_A + cur * 16384;
        const uint32_t Bb    = sbase + OFF_B + cur * 16384;
        const uint32_t BnOfs = OFF_B + (cur ^ 1) * 16384;      // OFFSET into smem

        if (hn) loadVh(vr, xb, n_base, i + 1, tid, 0);

        // compute ks = 0, 1
#pragma unroll
        for (int ks = 0; ks < 2; ks++) {
            uint32_t ah[2][4];
#pragma unroll
            for (int mt = 0; mt < 2; mt++) {
                uint32_t byte = (uint32_t)((a_row + mt * 16) * 128 + ks * 32 + a_kb);
                ldsm_x4(ah[mt], Ab + SW128(byte));
            }
            const int kc = ks * 16 + b_kcl;
            const uint32_t kb = (uint32_t)kc * 256;
            const uint32_t xm = ((uint32_t)kc & 7) << 4;
#pragma unroll
            for (int nt2 = 0; nt2 < 4; nt2++) {
                uint32_t br[4];
                const uint32_t nb = (uint32_t)(b_nbyte + nt2 * 32);
                ldsm_x4t(br, Bb + kb + (nb ^ xm));
#pragma unroll
                for (int mt = 0; mt < 2; mt++) {
                    mma16816(acc[mt][nt2 * 2 + 0], ah[mt], br[0], br[1]);
                    mma16816(acc[mt][nt2 * 2 + 1], ah[mt], br[2], br[3]);
                }
            }
        }

        if (hn) {
            convertBh(smem, BnOfs, vr, b, n_base, i + 1, tid, 0);   // B[nxt] half0
            loadVh(vr, xb, n_base, i + 1, tid, 1);
        }

        // compute ks = 2, 3
#pragma unroll
        for (int ks = 2; ks < 4; ks++) {
            uint32_t ah[2][4];
#pragma unroll
            for (int mt = 0; mt < 2; mt++) {
                uint32_t byte = (uint32_t)((a_row + mt * 16) * 128 + ks * 32 + a_kb);
                ldsm_x4(ah[mt], Ab + SW128(byte));
            }
            const int kc = ks * 16 + b_kcl;
            const uint32_t kb = (uint32_t)kc * 256;
            const uint32_t xm = ((uint32_t)kc & 7) << 4;
#pragma unroll
            for (int nt2 = 0; nt2 < 4; nt2++) {
                uint32_t br[4];
                const uint32_t nb = (uint32_t)(b_nbyte + nt2 * 32);
                ldsm_x4t(br, Bb + kb + (nb ^ xm));
#pragma unroll
                for (int mt = 0; mt < 2; mt++) {
                    mma16816(acc[mt][nt2 * 2 + 0], ah[mt], br[0], br[1]);
                    mma16816(acc[mt][nt2 * 2 + 1], ah[mt], br[2], br[3]);
                }
            }
        }

        if (hn) convertBh(smem, BnOfs, vr, b, n_base, i + 1, tid, 1);  // B[nxt] half1

        asm volatile("cp.async.wait_group 0;" ::: "memory");   // A[i+1] landed
        __syncthreads();    // B[nxt]+A[i+1] visible; A[cur]/B[cur] free
        if (i + 2 < NCHUNK) {
            const uint8_t* as = Asrc + (size_t)(i + 2) * 16384 + tid * 16;
            const uint32_t ad = sbase + OFF_A + cur * 16384 + tid * 16;
#pragma unroll
            for (int q = 0; q < 4; q++) cp16(ad + q * 4096, as + q * 4096);
            asm volatile("cp.async.commit_group;");
        }
    }

    // ---- epilogue ----
    float* bst = (float*)(smem + OFF_ST);
    bst[tid] = 0.f;
    __syncthreads();

    float s4[4] = {0.f, 0.f, 0.f, 0.f}, q4[4] = {0.f, 0.f, 0.f, 0.f};
#pragma unroll
    for (int mt = 0; mt < 2; mt++) {
        const int r0v = wm * 32 + mt * 16 + g;
        const int r1v = r0v + 8;
        const float b0v = bias[o_base + r0v];
        const float b1v = bias[o_base + r1v];
        float* p0 = out + ((size_t)b * COUT + o_base + r0v) * NP + n_base + wn * 64 + 2 * tg;
        float* p1 = out + ((size_t)b * COUT + o_base + r1v) * NP + n_base + wn * 64 + 2 * tg;
#pragma unroll
        for (int nt = 0; nt < 8; nt++) {
            float v0 = acc[mt][nt][0] + b0v;
            float v1 = acc[mt][nt][1] + b0v;
            float v2 = acc[mt][nt][2] + b1v;
            float v3 = acc[mt][nt][3] + b1v;
            *(float2*)(p0 + nt * 8) = make_float2(v0, v1);
            *(float2*)(p1 + nt * 8) = make_float2(v2, v3);
            s4[mt * 2 + 0] += v0 + v1;  q4[mt * 2 + 0] += v0 * v0 + v1 * v1;
            s4[mt * 2 + 1] += v2 + v3;  q4[mt * 2 + 1] += v2 * v2 + v3 * v3;
        }
    }
#pragma unroll
    for (int r = 0; r < 4; r++) {
        float s = s4[r], q = q4[r];
        s += __shfl_xor_sync(0xffffffffu, s, 1);
        s += __shfl_xor_sync(0xffffffffu, s, 2);
        q += __shfl_xor_sync(0xffffffffu, q, 1);
        q += __shfl_xor_sync(0xffffffffu, q, 2);
        if (tg == 0) {
            int lr = wm * 32 + (r >> 1) * 16 + (r & 1) * 8 + g;
            atomicAdd(&bst[lr], s);
            atomicAdd(&bst[128 + lr], q);
        }
    }
    __syncthreads();
    if (tid < 128) {
        atomicAdd(&g_sum[o_base + tid],   bst[tid]);
        atomicAdd(&g_sumsq[o_base + tid], bst[128 + tid]);
    }
}

// ---------------- kernel 4: finalize BN stats ----------------
__global__ void stats_kernel(const float* __restrict__ gamma,
                             const float* __restrict__ beta) {
    int c = threadIdx.x;
    const float inv_n = 1.0f / (float)(BB * NP);
    float mean = g_sum[c] * inv_n;
    float var  = g_sumsq[c] * inv_n - mean * mean;
    float inv  = 1.0f / sqrtf(var + 1e-5f);
    float sc   = gamma[c] * inv;
    g_scale[c] = sc;
    g_shift[c] = beta[c] - mean * sc;
}

// ---------------- kernel 5: apply BN + ReLU ----------------
__global__ void apply_kernel(float* __restrict__ out) {
    size_t i4 = (size_t)blockIdx.x * blockDim.x + threadIdx.x;
    float4 v = ((float4*)out)[i4];
    int o = (int)((i4 * 4) >> 13) & (COUT - 1);
    float s = g_scale[o], t = g_shift[o];
    v.x = fmaxf(v.x * s + t, 0.f);
    v.y = fmaxf(v.y * s + t, 0.f);
    v.z = fmaxf(v.z * s + t, 0.f);
    v.w = fmaxf(v.w * s + t, 0.f);
    ((float4*)out)[i4] = v;
}

// ---------------- launch ----------------
extern "C" void kernel_launch(void* const* d_in, const int* in_sizes, int n_in,
                              void* d_out, int out_size) {
    const float* x      = (const float*)d_in[0];
    const float* coords = (const float*)d_in[1];
    const float* rot    = (const float*)d_in[2];
    const float* dist   = (const float*)d_in[3];
    const float* W      = (const float*)d_in[4];
    const float* bias   = (const float*)d_in[5];
    const float* gamma  = (const float*)d_in[6];
    const float* beta   = (const float*)d_in[7];
    float* out = (float*)d_out;

    cudaFuncSetAttribute(conv11_kernel, cudaFuncAttributeMaxDynamicSharedMemorySize, SMEM_TOTAL);

    zero_sums_kernel<<<1, 256>>>();
    gweight_kernel<<<dim3(NP / 256, BB), 256>>>(coords, rot, dist);
    wsplit_kernel<<<(2 * NCHUNK * 128 * 64 + 255) / 256, 256>>>(W);
    conv11_kernel<<<dim3(NP / 128, COUT / 128, BB), 256, SMEM_TOTAL>>>(x, bias, out);
    stats_kernel<<<1, 256>>>(gamma, beta);
    apply_kernel<<<(BB * COUT * NP / 4) / 256, 256>>>(out);
}